// round 1
// baseline (speedup 1.0000x reference)
#include <cuda_runtime.h>
#include <math.h>
#include <stdint.h>

// Problem constants: B=4, N=1024, D=1024, H=16, HD=64, COND=256
// ada used chunks: 9 * D = 9216 columns

// ---------------------------------------------------------------------------
// Scratch (static __device__ arrays; allocation inside kernel_launch is banned)
// ---------------------------------------------------------------------------
__device__ float g_ada[4096ull * 9216ull];        // 151 MB
__device__ float g_xn[4096ull * 1024ull];         // ln+modulate output
__device__ float g_qkv[4096ull * 3072ull];        // q,k,v packed
__device__ float g_S[64ull * 1024ull * 2048ull];  // scores (max: cross, 512 MB)
__device__ float g_attn[4096ull * 1024ull];       // attention output (reused)
__device__ float g_qx1[4096ull * 1024ull];
__device__ float g_qc[4096ull * 1024ull];
__device__ float g_memln[8192ull * 1024ull];
__device__ float g_kv[8192ull * 2048ull];
__device__ float g_qx2[4096ull * 1024ull];
__device__ float g_h[4096ull * 4096ull];          // mlp hidden

// ---------------------------------------------------------------------------
// Generic NT GEMM: C[M,Nc] = A[M,K] @ W[Nc,K]^T  (both row-major, K contiguous)
// 128x128 tile, BK=16, 256 threads, 8x8 per-thread.
// EPI: 0=none 1=+bias 2=gelu(acc+bias) 3=resid+gate*acc 4=resid+gate*(acc+bias)
// ---------------------------------------------------------------------------
template<int EPI>
__global__ __launch_bounds__(256)
void gemm_nt(const float* __restrict__ A, const float* __restrict__ W,
             float* __restrict__ C, int M, int Nc, int K,
             const float* __restrict__ bias,
             const float* __restrict__ resid,
             const float* __restrict__ gate, int gate_ld)
{
    __shared__ float As[16][128];
    __shared__ float Bs[16][128];
    const int tid = threadIdx.x;
    const int bm = blockIdx.y * 128;
    const int bn = blockIdx.x * 128;
    const int tx = tid & 15;
    const int ty = tid >> 4;

    float acc[8][8];
#pragma unroll
    for (int i = 0; i < 8; i++)
#pragma unroll
        for (int j = 0; j < 8; j++) acc[i][j] = 0.0f;

    const int lrow = tid >> 2;  // 0..63
    const int lc4  = tid & 3;   // 0..3 (float4 column within 16-wide K tile)

    for (int k0 = 0; k0 < K; k0 += 16) {
#pragma unroll
        for (int half = 0; half < 2; half++) {
            int row = lrow + half * 64;
            float4 va = *reinterpret_cast<const float4*>(A + (size_t)(bm + row) * K + k0 + lc4 * 4);
            As[lc4 * 4 + 0][row] = va.x;
            As[lc4 * 4 + 1][row] = va.y;
            As[lc4 * 4 + 2][row] = va.z;
            As[lc4 * 4 + 3][row] = va.w;
            float4 vb = *reinterpret_cast<const float4*>(W + (size_t)(bn + row) * K + k0 + lc4 * 4);
            Bs[lc4 * 4 + 0][row] = vb.x;
            Bs[lc4 * 4 + 1][row] = vb.y;
            Bs[lc4 * 4 + 2][row] = vb.z;
            Bs[lc4 * 4 + 3][row] = vb.w;
        }
        __syncthreads();
#pragma unroll
        for (int kk = 0; kk < 16; kk++) {
            float a[8], b[8];
            *reinterpret_cast<float4*>(&a[0]) = *reinterpret_cast<const float4*>(&As[kk][ty * 8]);
            *reinterpret_cast<float4*>(&a[4]) = *reinterpret_cast<const float4*>(&As[kk][ty * 8 + 4]);
            *reinterpret_cast<float4*>(&b[0]) = *reinterpret_cast<const float4*>(&Bs[kk][tx * 8]);
            *reinterpret_cast<float4*>(&b[4]) = *reinterpret_cast<const float4*>(&Bs[kk][tx * 8 + 4]);
#pragma unroll
            for (int i = 0; i < 8; i++)
#pragma unroll
                for (int j = 0; j < 8; j++)
                    acc[i][j] += a[i] * b[j];
        }
        __syncthreads();
    }

#pragma unroll
    for (int i = 0; i < 8; i++) {
        int m = bm + ty * 8 + i;
#pragma unroll
        for (int j = 0; j < 8; j++) {
            int n = bn + tx * 8 + j;
            float v = acc[i][j];
            if (EPI == 1 || EPI == 2 || EPI == 4) v += bias[n];
            if (EPI == 2) {
                float x = v;
                v = 0.5f * x * (1.0f + tanhf(0.7978845608028654f * (x + 0.044715f * x * x * x)));
            }
            if (EPI == 3 || EPI == 4)
                v = resid[(size_t)m * Nc + n] + gate[(size_t)m * gate_ld + n] * v;
            C[(size_t)m * Nc + n] = v;
        }
    }
}

// ---------------------------------------------------------------------------
// LayerNorm (+ optional adaLN modulate). One block per token row, D=1024.
// ---------------------------------------------------------------------------
__global__ __launch_bounds__(256)
void ln_mod_kernel(const float* __restrict__ x, const float* __restrict__ w,
                   const float* __restrict__ ada, int shoff, int scoff,
                   float* __restrict__ out)
{
    const int row = blockIdx.x;
    const int tid = threadIdx.x;
    const float* xr = x + (size_t)row * 1024;
    float4 v = *reinterpret_cast<const float4*>(xr + tid * 4);
    float s  = v.x + v.y + v.z + v.w;
    float s2 = v.x * v.x + v.y * v.y + v.z * v.z + v.w * v.w;
    __shared__ float shs[8], shs2[8], stat[2];
#pragma unroll
    for (int o = 16; o; o >>= 1) {
        s  += __shfl_xor_sync(0xffffffffu, s, o);
        s2 += __shfl_xor_sync(0xffffffffu, s2, o);
    }
    if ((tid & 31) == 0) { shs[tid >> 5] = s; shs2[tid >> 5] = s2; }
    __syncthreads();
    if (tid == 0) {
        float a = 0.f, b2 = 0.f;
#pragma unroll
        for (int i = 0; i < 8; i++) { a += shs[i]; b2 += shs2[i]; }
        float mean = a * (1.0f / 1024.0f);
        float var  = b2 * (1.0f / 1024.0f) - mean * mean;
        stat[0] = mean;
        stat[1] = rsqrtf(var + 1e-5f);
    }
    __syncthreads();
    float mean = stat[0], rstd = stat[1];
    float4 wv  = *reinterpret_cast<const float4*>(w + tid * 4);
    const float* adar = ada + (size_t)row * 9216;
    float4 sh4 = *reinterpret_cast<const float4*>(adar + shoff + tid * 4);
    float4 sc4 = *reinterpret_cast<const float4*>(adar + scoff + tid * 4);
    float4 o;
    o.x = (v.x - mean) * rstd * wv.x * (1.0f + sc4.x) + sh4.x;
    o.y = (v.y - mean) * rstd * wv.y * (1.0f + sc4.y) + sh4.y;
    o.z = (v.z - mean) * rstd * wv.z * (1.0f + sc4.z) + sh4.z;
    o.w = (v.w - mean) * rstd * wv.w * (1.0f + sc4.w) + sh4.w;
    *reinterpret_cast<float4*>(out + (size_t)row * 1024 + tid * 4) = o;
}

// LayerNorm of concat(h_content, h_obs); one block per memory row (B*2N rows)
__global__ __launch_bounds__(256)
void memln_kernel(const float* __restrict__ hc, const float* __restrict__ ho,
                  const float* __restrict__ w, float* __restrict__ out)
{
    const int row = blockIdx.x;  // b*2048 + j
    const int b = row >> 11, j = row & 2047;
    const float* src = (j < 1024) ? (hc + ((size_t)b * 1024 + j) * 1024)
                                  : (ho + ((size_t)b * 1024 + (j - 1024)) * 1024);
    const int tid = threadIdx.x;
    float4 v = *reinterpret_cast<const float4*>(src + tid * 4);
    float s  = v.x + v.y + v.z + v.w;
    float s2 = v.x * v.x + v.y * v.y + v.z * v.z + v.w * v.w;
    __shared__ float shs[8], shs2[8], stat[2];
#pragma unroll
    for (int o = 16; o; o >>= 1) {
        s  += __shfl_xor_sync(0xffffffffu, s, o);
        s2 += __shfl_xor_sync(0xffffffffu, s2, o);
    }
    if ((tid & 31) == 0) { shs[tid >> 5] = s; shs2[tid >> 5] = s2; }
    __syncthreads();
    if (tid == 0) {
        float a = 0.f, b2 = 0.f;
#pragma unroll
        for (int i = 0; i < 8; i++) { a += shs[i]; b2 += shs2[i]; }
        float mean = a * (1.0f / 1024.0f);
        float var  = b2 * (1.0f / 1024.0f) - mean * mean;
        stat[0] = mean;
        stat[1] = rsqrtf(var + 1e-5f);
    }
    __syncthreads();
    float mean = stat[0], rstd = stat[1];
    float4 wv = *reinterpret_cast<const float4*>(w + tid * 4);
    float4 o;
    o.x = (v.x - mean) * rstd * wv.x;
    o.y = (v.y - mean) * rstd * wv.y;
    o.z = (v.z - mean) * rstd * wv.z;
    o.w = (v.w - mean) * rstd * wv.w;
    *reinterpret_cast<float4*>(out + (size_t)row * 1024 + tid * 4) = o;
}

// ---------------------------------------------------------------------------
// RoPE (in place). half rotation: out[:32]=x1*c-x2*s ; out[32:]=x2*c+x1*s
// ---------------------------------------------------------------------------
__global__ void rope_qk_kernel(float* __restrict__ qkv, const float* __restrict__ ct,
                               const float* __restrict__ st)
{
    const int bn = blockIdx.x;        // b*N + n
    const int n = bn & 1023;
    const int h = threadIdx.x >> 5;
    const int d = threadIdx.x & 31;
    const float c = ct[n * 64 + d];
    const float s = st[n * 64 + d];
    float* base = qkv + (size_t)bn * 3072 + h * 64;
#pragma unroll
    for (int plane = 0; plane < 2; plane++) {
        float* p = base + plane * 1024;
        float x1 = p[d], x2 = p[d + 32];
        p[d]      = x1 * c - x2 * s;
        p[d + 32] = x2 * c + x1 * s;
    }
}

__global__ void rope_rows_kernel(float* __restrict__ x, const float* __restrict__ ct,
                                 const float* __restrict__ st, int rowlen)
{
    const int r = blockIdx.x;
    const int n = r & 1023;           // pos = token % N (works for both q and kc)
    const int h = threadIdx.x >> 5;
    const int d = threadIdx.x & 31;
    const float c = ct[n * 64 + d];
    const float s = st[n * 64 + d];
    float* p = x + (size_t)r * rowlen + h * 64;
    float x1 = p[d], x2 = p[d + 32];
    p[d]      = x1 * c - x2 * s;
    p[d + 32] = x2 * c + x1 * s;
}

// ---------------------------------------------------------------------------
// Attention scores: S[z, q, k] = scale * (Q_row . K_row) + mask[b, q, k]
// HD=64 fits entirely in smem -> no K-dim loop. 64x64 output tile per block.
// ---------------------------------------------------------------------------
__global__ __launch_bounds__(256)
void attn_scores_kernel(const float* __restrict__ Q, long long qbatch, int qstride,
                        const float* __restrict__ Kp, long long kbatch, int kstride,
                        const float* __restrict__ mask, int mask_ld,
                        float* __restrict__ S, int s_ld, float scale)
{
    const int z = blockIdx.z;         // b*H + h
    const int b = z >> 4;
    const int h = z & 15;
    const float* qb = Q  + (size_t)b * qbatch + h * 64;
    const float* kb = Kp + (size_t)b * kbatch + h * 64;
    const int q0 = blockIdx.x * 64;
    const int k0 = blockIdx.y * 64;

    __shared__ float Qs[64 * 68];   // [d][qrow]
    __shared__ float Ks[64 * 68];   // [d][kcol]
    const int tid = threadIdx.x;
#pragma unroll
    for (int i = 0; i < 4; i++) {
        int fid = tid + i * 256;    // 1024 float4s
        int row = fid >> 4;
        int c4  = fid & 15;
        float4 v = *reinterpret_cast<const float4*>(qb + (size_t)(q0 + row) * qstride + c4 * 4);
        Qs[(c4 * 4 + 0) * 68 + row] = v.x;
        Qs[(c4 * 4 + 1) * 68 + row] = v.y;
        Qs[(c4 * 4 + 2) * 68 + row] = v.z;
        Qs[(c4 * 4 + 3) * 68 + row] = v.w;
        float4 u = *reinterpret_cast<const float4*>(kb + (size_t)(k0 + row) * kstride + c4 * 4);
        Ks[(c4 * 4 + 0) * 68 + row] = u.x;
        Ks[(c4 * 4 + 1) * 68 + row] = u.y;
        Ks[(c4 * 4 + 2) * 68 + row] = u.z;
        Ks[(c4 * 4 + 3) * 68 + row] = u.w;
    }
    __syncthreads();

    const int tx = tid & 15, ty = tid >> 4;
    float acc[4][4];
#pragma unroll
    for (int i = 0; i < 4; i++)
#pragma unroll
        for (int j = 0; j < 4; j++) acc[i][j] = 0.0f;

#pragma unroll
    for (int d = 0; d < 64; d++) {
        float4 a  = *reinterpret_cast<const float4*>(Qs + d * 68 + ty * 4);
        float4 bb = *reinterpret_cast<const float4*>(Ks + d * 68 + tx * 4);
        float av[4] = {a.x, a.y, a.z, a.w};
        float bv[4] = {bb.x, bb.y, bb.z, bb.w};
#pragma unroll
        for (int i = 0; i < 4; i++)
#pragma unroll
            for (int j = 0; j < 4; j++)
                acc[i][j] += av[i] * bv[j];
    }

#pragma unroll
    for (int i = 0; i < 4; i++) {
        int qg = q0 + ty * 4 + i;
        const float* mp = mask + ((size_t)b * 1024 + qg) * mask_ld + k0 + tx * 4;
        float* sp = S + ((size_t)z * 1024 + qg) * s_ld + k0 + tx * 4;
        float4 o;
        o.x = acc[i][0] * scale + mp[0];
        o.y = acc[i][1] * scale + mp[1];
        o.z = acc[i][2] * scale + mp[2];
        o.w = acc[i][3] * scale + mp[3];
        *reinterpret_cast<float4*>(sp) = o;
    }
}

// ---------------------------------------------------------------------------
// Row softmax over length L (1024 or 2048)
// ---------------------------------------------------------------------------
template<int L>
__global__ __launch_bounds__(256)
void softmax_kernel(float* __restrict__ S)
{
    constexpr int PER = L / 1024;   // float4s per thread
    float* p = S + (size_t)blockIdx.x * L;
    const int tid = threadIdx.x;
    float4 v[PER];
    float m = -3.4e38f;
#pragma unroll
    for (int i = 0; i < PER; i++) {
        v[i] = *reinterpret_cast<const float4*>(p + (tid + i * 256) * 4);
        m = fmaxf(m, fmaxf(fmaxf(v[i].x, v[i].y), fmaxf(v[i].z, v[i].w)));
    }
    __shared__ float smA[8], smB[8], stat[2];
#pragma unroll
    for (int o = 16; o; o >>= 1) m = fmaxf(m, __shfl_xor_sync(0xffffffffu, m, o));
    if ((tid & 31) == 0) smA[tid >> 5] = m;
    __syncthreads();
    if (tid == 0) {
        float a = smA[0];
#pragma unroll
        for (int i = 1; i < 8; i++) a = fmaxf(a, smA[i]);
        stat[0] = a;
    }
    __syncthreads();
    m = stat[0];
    float s = 0.0f;
#pragma unroll
    for (int i = 0; i < PER; i++) {
        v[i].x = __expf(v[i].x - m);
        v[i].y = __expf(v[i].y - m);
        v[i].z = __expf(v[i].z - m);
        v[i].w = __expf(v[i].w - m);
        s += v[i].x + v[i].y + v[i].z + v[i].w;
    }
#pragma unroll
    for (int o = 16; o; o >>= 1) s += __shfl_xor_sync(0xffffffffu, s, o);
    if ((tid & 31) == 0) smB[tid >> 5] = s;
    __syncthreads();
    if (tid == 0) {
        float a = 0.f;
#pragma unroll
        for (int i = 0; i < 8; i++) a += smB[i];
        stat[1] = a;
    }
    __syncthreads();
    float inv = 1.0f / stat[1];
#pragma unroll
    for (int i = 0; i < PER; i++) {
        v[i].x *= inv; v[i].y *= inv; v[i].z *= inv; v[i].w *= inv;
        *reinterpret_cast<float4*>(p + (tid + i * 256) * 4) = v[i];
    }
}

// ---------------------------------------------------------------------------
// P @ V: O[b, q, h*64 + d] = sum_k P[z,q,k] V[b,k,h,d]. 64 q-rows per block.
// ---------------------------------------------------------------------------
__global__ __launch_bounds__(256)
void attn_pv_kernel(const float* __restrict__ P, int p_ld,
                    const float* __restrict__ V, long long vbatch, int vstride,
                    float* __restrict__ O, int Lk)
{
    const int z = blockIdx.y;
    const int b = z >> 4;
    const int h = z & 15;
    const int q0 = blockIdx.x * 64;
    const float* pb = P + ((size_t)z * 1024 + q0) * p_ld;
    const float* vb = V + (size_t)b * vbatch + h * 64;

    __shared__ float Ps[64 * 68];   // [k][qrow]
    __shared__ float Vs[64 * 68];   // [k][d]
    const int tid = threadIdx.x;
    const int tx = tid & 15, ty = tid >> 4;

    float acc[4][4];
#pragma unroll
    for (int i = 0; i < 4; i++)
#pragma unroll
        for (int j = 0; j < 4; j++) acc[i][j] = 0.0f;

    for (int kt = 0; kt < Lk; kt += 64) {
#pragma unroll
        for (int i = 0; i < 4; i++) {
            int fid = tid + i * 256;
            int row = fid >> 4;
            int c4  = fid & 15;
            float4 v = *reinterpret_cast<const float4*>(pb + (size_t)row * p_ld + kt + c4 * 4);
            Ps[(c4 * 4 + 0) * 68 + row] = v.x;
            Ps[(c4 * 4 + 1) * 68 + row] = v.y;
            Ps[(c4 * 4 + 2) * 68 + row] = v.z;
            Ps[(c4 * 4 + 3) * 68 + row] = v.w;
            float4 u = *reinterpret_cast<const float4*>(vb + (size_t)(kt + row) * vstride + c4 * 4);
            *reinterpret_cast<float4*>(Vs + row * 68 + c4 * 4) = u;
        }
        __syncthreads();
#pragma unroll
        for (int kk = 0; kk < 64; kk++) {
            float4 a  = *reinterpret_cast<const float4*>(Ps + kk * 68 + ty * 4);
            float4 bb = *reinterpret_cast<const float4*>(Vs + kk * 68 + tx * 4);
            float av[4] = {a.x, a.y, a.z, a.w};
            float bv[4] = {bb.x, bb.y, bb.z, bb.w};
#pragma unroll
            for (int i = 0; i < 4; i++)
#pragma unroll
                for (int j = 0; j < 4; j++)
                    acc[i][j] += av[i] * bv[j];
        }
        __syncthreads();
    }

#pragma unroll
    for (int i = 0; i < 4; i++) {
        int qg = q0 + ty * 4 + i;
        float* op = O + ((size_t)b * 1024 + qg) * 1024 + h * 64 + tx * 4;
        *reinterpret_cast<float4*>(op) = make_float4(acc[i][0], acc[i][1], acc[i][2], acc[i][3]);
    }
}

// ---------------------------------------------------------------------------
// Launch sequence
// ---------------------------------------------------------------------------
extern "C" void kernel_launch(void* const* d_in, const int* in_sizes, int n_in,
                              void* d_out, int out_size)
{
    const float* q_x       = (const float*)d_in[0];
    const float* h_content = (const float*)d_in[1];
    const float* h_obs     = (const float*)d_in[2];
    const float* t_cond    = (const float*)d_in[3];
    const float* cosT      = (const float*)d_in[4];
    const float* sinT      = (const float*)d_in[5];
    const float* M_QQ      = (const float*)d_in[6];
    const float* M_hyb     = (const float*)d_in[7];
    const float* w_ln_self = (const float*)d_in[8];
    const float* w_qkv     = (const float*)d_in[9];
    const float* w_self_out= (const float*)d_in[10];
    const float* w_ln_cross= (const float*)d_in[11];
    const float* w_ln_mem  = (const float*)d_in[12];
    const float* w_qproj   = (const float*)d_in[13];
    const float* w_kvproj  = (const float*)d_in[14];
    const float* w_cross_out=(const float*)d_in[15];
    const float* w_ln_mlp  = (const float*)d_in[16];
    const float* w_mlp1    = (const float*)d_in[17];
    const float* b_mlp1    = (const float*)d_in[18];
    const float* w_mlp2    = (const float*)d_in[19];
    const float* b_mlp2    = (const float*)d_in[20];
    const float* w_ada     = (const float*)d_in[21];
    const float* b_ada     = (const float*)d_in[22];
    float* out = (float*)d_out;

    float *ada, *xn, *qkv, *S, *attn, *qx1, *qc, *memln, *kv, *qx2, *hbuf;
    cudaGetSymbolAddress((void**)&ada,   g_ada);
    cudaGetSymbolAddress((void**)&xn,    g_xn);
    cudaGetSymbolAddress((void**)&qkv,   g_qkv);
    cudaGetSymbolAddress((void**)&S,     g_S);
    cudaGetSymbolAddress((void**)&attn,  g_attn);
    cudaGetSymbolAddress((void**)&qx1,   g_qx1);
    cudaGetSymbolAddress((void**)&qc,    g_qc);
    cudaGetSymbolAddress((void**)&memln, g_memln);
    cudaGetSymbolAddress((void**)&kv,    g_kv);
    cudaGetSymbolAddress((void**)&qx2,   g_qx2);
    cudaGetSymbolAddress((void**)&hbuf,  g_h);

    const float scale = 0.125f;  // 1/sqrt(64)

    // 1. ada (first 9 chunks only): [4096,9216] = t_cond @ w_ada[:9216].T + b_ada
    gemm_nt<1><<<dim3(72, 32), 256>>>(t_cond, w_ada, ada, 4096, 9216, 256,
                                      b_ada, nullptr, nullptr, 0);
    // 2. xn = modulate(ln(q_x, w_ln_self), sh_s, sc_s)
    ln_mod_kernel<<<4096, 256>>>(q_x, w_ln_self, ada, 0 * 1024, 1 * 1024, xn);
    // 3. qkv = xn @ w_qkv.T
    gemm_nt<0><<<dim3(24, 32), 256>>>(xn, w_qkv, qkv, 4096, 3072, 1024,
                                      nullptr, nullptr, nullptr, 0);
    // 4. RoPE on q and k planes (in place)
    rope_qk_kernel<<<4096, 512>>>(qkv, cosT, sinT);
    // 5-7. self attention
    attn_scores_kernel<<<dim3(16, 16, 64), 256>>>(
        qkv, 1024LL * 3072, 3072, qkv + 1024, 1024LL * 3072, 3072,
        M_QQ, 1024, S, 1024, scale);
    softmax_kernel<1024><<<65536, 256>>>(S);
    attn_pv_kernel<<<dim3(16, 64), 256>>>(S, 1024, qkv + 2048, 1024LL * 3072, 3072,
                                          attn, 1024);
    // 8. qx1 = q_x + g_s * (attn @ w_self_out.T)
    gemm_nt<3><<<dim3(8, 32), 256>>>(attn, w_self_out, qx1, 4096, 1024, 1024,
                                     nullptr, q_x, ada + 2 * 1024, 9216);
    // 9. xn = modulate(ln(qx1, w_ln_cross), sh_c, sc_c)
    ln_mod_kernel<<<4096, 256>>>(qx1, w_ln_cross, ada, 3 * 1024, 4 * 1024, xn);
    // 10. qc = xn @ w_qproj.T
    gemm_nt<0><<<dim3(8, 32), 256>>>(xn, w_qproj, qc, 4096, 1024, 1024,
                                     nullptr, nullptr, nullptr, 0);
    // 11. RoPE on qc
    rope_rows_kernel<<<4096, 512>>>(qc, cosT, sinT, 1024);
    // 12. memln = ln(concat(h_content, h_obs), w_ln_mem)
    memln_kernel<<<8192, 256>>>(h_content, h_obs, w_ln_mem, memln);
    // 13. kv = memln @ w_kvproj.T   [8192, 2048]
    gemm_nt<0><<<dim3(16, 64), 256>>>(memln, w_kvproj, kv, 8192, 2048, 1024,
                                      nullptr, nullptr, nullptr, 0);
    // 14. RoPE on kc (first 1024 of each kv row; pos = token % N)
    rope_rows_kernel<<<8192, 512>>>(kv, cosT, sinT, 2048);
    // 15-17. cross attention (Lk = 2048)
    attn_scores_kernel<<<dim3(16, 32, 64), 256>>>(
        qc, 1024LL * 1024, 1024, kv, 2048LL * 2048, 2048,
        M_hyb, 2048, S, 2048, scale);
    softmax_kernel<2048><<<65536, 256>>>(S);
    attn_pv_kernel<<<dim3(16, 64), 256>>>(S, 2048, kv + 1024, 2048LL * 2048, 2048,
                                          attn, 2048);
    // 18. qx2 = qx1 + g_c * (attn @ w_cross_out.T)
    gemm_nt<3><<<dim3(8, 32), 256>>>(attn, w_cross_out, qx2, 4096, 1024, 1024,
                                     nullptr, qx1, ada + 5 * 1024, 9216);
    // 19. xn = modulate(ln(qx2, w_ln_mlp), sh_m, sc_m)
    ln_mod_kernel<<<4096, 256>>>(qx2, w_ln_mlp, ada, 6 * 1024, 7 * 1024, xn);
    // 20. h = gelu(xn @ w_mlp1.T + b_mlp1)
    gemm_nt<2><<<dim3(32, 32), 256>>>(xn, w_mlp1, hbuf, 4096, 4096, 1024,
                                      b_mlp1, nullptr, nullptr, 0);
    // 21. out = qx2 + g_m * (h @ w_mlp2.T + b_mlp2)
    gemm_nt<4><<<dim3(8, 32), 256>>>(hbuf, w_mlp2, out, 4096, 1024, 4096,
                                     b_mlp2, qx2, ada + 8 * 1024, 9216);
}

// round 3
// speedup vs baseline: 2.2404x; 2.2404x over previous
#include <cuda_runtime.h>
#include <math.h>
#include <stdint.h>

// Problem constants: B=4, N=1024, D=1024, H=16, HD=64, COND=256
// ada used chunks: 9 * D = 9216 columns

// ---------------------------------------------------------------------------
// Scratch (static __device__ arrays; allocation inside kernel_launch is banned)
// ---------------------------------------------------------------------------
__device__ float g_ada[4096ull * 9216ull];
__device__ float g_xn[4096ull * 1024ull];
__device__ float g_qkv[4096ull * 3072ull];
__device__ float g_S[64ull * 1024ull * 2048ull];
__device__ float g_attn[4096ull * 1024ull];
__device__ float g_qx1[4096ull * 1024ull];
__device__ float g_qc[4096ull * 1024ull];
__device__ float g_memln[8192ull * 1024ull];
__device__ float g_kv[8192ull * 2048ull];
__device__ float g_qx2[4096ull * 1024ull];
__device__ float g_h[4096ull * 4096ull];

// ---------------------------------------------------------------------------
// tf32 helpers
// ---------------------------------------------------------------------------
__device__ __forceinline__ uint32_t f2tf32(float x) {
    uint32_t u;
    asm("cvt.rna.tf32.f32 %0, %1;" : "=r"(u) : "f"(x));
    return u;
}

__device__ __forceinline__ void mma8(float* d, const uint32_t* a, const uint32_t* b) {
    asm volatile(
        "mma.sync.aligned.m16n8k8.row.col.f32.tf32.tf32.f32 "
        "{%0,%1,%2,%3}, {%4,%5,%6,%7}, {%8,%9}, {%0,%1,%2,%3};"
        : "+f"(d[0]), "+f"(d[1]), "+f"(d[2]), "+f"(d[3])
        : "r"(a[0]), "r"(a[1]), "r"(a[2]), "r"(a[3]), "r"(b[0]), "r"(b[1]));
}

// ---------------------------------------------------------------------------
// TF32 tensor-core GEMM.
//  C[M,Nc] = A[M,K] @ B^T where:
//   BMODE=0: B given as W[Nc,K] row-major (K contiguous)   -> weights / K-matrix
//   BMODE=1: B given as V[K,Nc] row-major (Nc contiguous)  -> P@V case
//  MODE=0: plain (grid.z=1)
//  MODE=1: attention scores: A,B head-batched (z=b*16+h), C per z, mask per b
//  MODE=2: PV: A per z (probs), B,C head-batched
//  EPI: 0=none 1=+bias 2=gelu(acc+bias) 3=resid+gate*acc 4=resid+gate*(acc+bias)
//       5=acc*scale+mask
// ---------------------------------------------------------------------------
template<int BM, int BN, int WARPS_M, int WARPS_N, int BMODE, int MODE, int EPI>
__global__ __launch_bounds__(256)
void gemm_tf32(const float* __restrict__ A, long long abatch, int lda,
               const float* __restrict__ Bm, long long bbatch, int ldb,
               float* __restrict__ C, long long cbatch, int ldc,
               int M, int Nc, int K,
               const float* __restrict__ bias,
               const float* __restrict__ resid,
               const float* __restrict__ gate, int gate_ld,
               const float* __restrict__ mask, int mask_ld, float scale)
{
    constexpr int BK = 16;
    constexpr int WM = BM / WARPS_M;
    constexpr int WN = BN / WARPS_N;
    constexpr int MT = WM / 16;
    constexpr int NT = WN / 8;
    constexpr int AS_STRIDE = BK + 4;      // 20: conflict-free frag reads
    constexpr int BS_STRIDE_NK = BK + 4;   // 20
    constexpr int BS_STRIDE_KN = BN + 8;   // e.g. 72: conflict-free frag reads

    __shared__ float As[BM * AS_STRIDE];
    __shared__ float Bs[BMODE == 0 ? BN * BS_STRIDE_NK : BK * BS_STRIDE_KN];

    const int tid = threadIdx.x;
    const int lane = tid & 31;
    const int wid = tid >> 5;
    const int wm = wid / WARPS_N;
    const int wn = wid % WARPS_N;
    const int g = lane >> 2;
    const int tg = lane & 3;

    const int bm = blockIdx.y * BM;
    const int bn = blockIdx.x * BN;
    const int z = blockIdx.z;

    const float* Ap = A;
    const float* Bp = Bm;
    float* Cp = C;
    const float* maskp = mask;
    if (MODE == 1) {
        Ap += (size_t)(z >> 4) * abatch + (size_t)(z & 15) * 64;
        Bp += (size_t)(z >> 4) * bbatch + (size_t)(z & 15) * 64;
        Cp += (size_t)z * cbatch;
        maskp += (size_t)(z >> 4) * 1024 * (size_t)mask_ld;
    } else if (MODE == 2) {
        Ap += (size_t)z * abatch;
        Bp += (size_t)(z >> 4) * bbatch + (size_t)(z & 15) * 64;
        Cp += (size_t)(z >> 4) * cbatch + (size_t)(z & 15) * 64;
    }

    float acc[MT][NT][4];
#pragma unroll
    for (int mt = 0; mt < MT; mt++)
#pragma unroll
        for (int nt = 0; nt < NT; nt++)
#pragma unroll
            for (int i = 0; i < 4; i++) acc[mt][nt][i] = 0.0f;

    for (int k0 = 0; k0 < K; k0 += BK) {
        // ---- load A tile (BM x 16), row-major, cvt to tf32 ----
#pragma unroll
        for (int i = 0; i < BM * 4 / 256; i++) {
            int idx = tid + i * 256;
            int row = idx >> 2, c4 = idx & 3;
            float4 v = *reinterpret_cast<const float4*>(
                Ap + (size_t)(bm + row) * lda + k0 + c4 * 4);
            uint32_t* dst = reinterpret_cast<uint32_t*>(&As[row * AS_STRIDE + c4 * 4]);
            dst[0] = f2tf32(v.x); dst[1] = f2tf32(v.y);
            dst[2] = f2tf32(v.z); dst[3] = f2tf32(v.w);
        }
        // ---- load B tile ----
        if (BMODE == 0) {
#pragma unroll
            for (int i = 0; i < BN * 4 / 256; i++) {
                int idx = tid + i * 256;
                int row = idx >> 2, c4 = idx & 3;
                float4 v = *reinterpret_cast<const float4*>(
                    Bp + (size_t)(bn + row) * ldb + k0 + c4 * 4);
                uint32_t* dst = reinterpret_cast<uint32_t*>(&Bs[row * BS_STRIDE_NK + c4 * 4]);
                dst[0] = f2tf32(v.x); dst[1] = f2tf32(v.y);
                dst[2] = f2tf32(v.z); dst[3] = f2tf32(v.w);
            }
        } else {
#pragma unroll
            for (int i = 0; i < BK * BN / 4 / 256; i++) {
                int idx = tid + i * 256;
                int k = idx / (BN / 4), c4 = idx % (BN / 4);
                float4 v = *reinterpret_cast<const float4*>(
                    Bp + (size_t)(k0 + k) * ldb + bn + c4 * 4);
                uint32_t* dst = reinterpret_cast<uint32_t*>(&Bs[k * BS_STRIDE_KN + c4 * 4]);
                dst[0] = f2tf32(v.x); dst[1] = f2tf32(v.y);
                dst[2] = f2tf32(v.z); dst[3] = f2tf32(v.w);
            }
        }
        __syncthreads();

#pragma unroll
        for (int kk = 0; kk < BK; kk += 8) {
            uint32_t af[MT][4];
            uint32_t bf[NT][2];
#pragma unroll
            for (int mt = 0; mt < MT; mt++) {
                int r = wm * WM + mt * 16;
                af[mt][0] = __float_as_uint(As[(r + g) * AS_STRIDE + kk + tg]);
                af[mt][1] = __float_as_uint(As[(r + g + 8) * AS_STRIDE + kk + tg]);
                af[mt][2] = __float_as_uint(As[(r + g) * AS_STRIDE + kk + tg + 4]);
                af[mt][3] = __float_as_uint(As[(r + g + 8) * AS_STRIDE + kk + tg + 4]);
            }
#pragma unroll
            for (int nt = 0; nt < NT; nt++) {
                int c = wn * WN + nt * 8 + g;
                if (BMODE == 0) {
                    bf[nt][0] = __float_as_uint(Bs[c * BS_STRIDE_NK + kk + tg]);
                    bf[nt][1] = __float_as_uint(Bs[c * BS_STRIDE_NK + kk + tg + 4]);
                } else {
                    bf[nt][0] = __float_as_uint(Bs[(kk + tg) * BS_STRIDE_KN + c]);
                    bf[nt][1] = __float_as_uint(Bs[(kk + tg + 4) * BS_STRIDE_KN + c]);
                }
            }
#pragma unroll
            for (int mt = 0; mt < MT; mt++)
#pragma unroll
                for (int nt = 0; nt < NT; nt++)
                    mma8(acc[mt][nt], af[mt], bf[nt]);
        }
        __syncthreads();
    }

    // ---- epilogue ----
#pragma unroll
    for (int mt = 0; mt < MT; mt++) {
#pragma unroll
        for (int nt = 0; nt < NT; nt++) {
            int m0 = bm + wm * WM + mt * 16 + g;
            int n0 = bn + wn * WN + nt * 8 + 2 * tg;
#pragma unroll
            for (int r = 0; r < 2; r++) {
                int m = m0 + r * 8;
#pragma unroll
                for (int cc = 0; cc < 2; cc++) {
                    int n = n0 + cc;
                    float v = acc[mt][nt][r * 2 + cc];
                    if (EPI == 1 || EPI == 2 || EPI == 4) v += bias[n];
                    if (EPI == 2) {
                        float x = v;
                        v = 0.5f * x * (1.0f + tanhf(0.7978845608028654f *
                                                     (x + 0.044715f * x * x * x)));
                    }
                    if (EPI == 3 || EPI == 4)
                        v = resid[(size_t)m * ldc + n] + gate[(size_t)m * gate_ld + n] * v;
                    if (EPI == 5)
                        v = v * scale + maskp[(size_t)m * mask_ld + n];
                    Cp[(size_t)m * ldc + n] = v;
                }
            }
        }
    }
}

// ---------------------------------------------------------------------------
// LayerNorm (+ adaLN modulate). One block per token row, D=1024.
// ---------------------------------------------------------------------------
__global__ __launch_bounds__(256)
void ln_mod_kernel(const float* __restrict__ x, const float* __restrict__ w,
                   const float* __restrict__ ada, int shoff, int scoff,
                   float* __restrict__ out)
{
    const int row = blockIdx.x;
    const int tid = threadIdx.x;
    const float* xr = x + (size_t)row * 1024;
    float4 v = *reinterpret_cast<const float4*>(xr + tid * 4);
    float s  = v.x + v.y + v.z + v.w;
    float s2 = v.x * v.x + v.y * v.y + v.z * v.z + v.w * v.w;
    __shared__ float shs[8], shs2[8], stat[2];
#pragma unroll
    for (int o = 16; o; o >>= 1) {
        s  += __shfl_xor_sync(0xffffffffu, s, o);
        s2 += __shfl_xor_sync(0xffffffffu, s2, o);
    }
    if ((tid & 31) == 0) { shs[tid >> 5] = s; shs2[tid >> 5] = s2; }
    __syncthreads();
    if (tid == 0) {
        float a = 0.f, b2 = 0.f;
#pragma unroll
        for (int i = 0; i < 8; i++) { a += shs[i]; b2 += shs2[i]; }
        float mean = a * (1.0f / 1024.0f);
        float var  = b2 * (1.0f / 1024.0f) - mean * mean;
        stat[0] = mean;
        stat[1] = rsqrtf(var + 1e-5f);
    }
    __syncthreads();
    float mean = stat[0], rstd = stat[1];
    float4 wv  = *reinterpret_cast<const float4*>(w + tid * 4);
    const float* adar = ada + (size_t)row * 9216;
    float4 sh4 = *reinterpret_cast<const float4*>(adar + shoff + tid * 4);
    float4 sc4 = *reinterpret_cast<const float4*>(adar + scoff + tid * 4);
    float4 o;
    o.x = (v.x - mean) * rstd * wv.x * (1.0f + sc4.x) + sh4.x;
    o.y = (v.y - mean) * rstd * wv.y * (1.0f + sc4.y) + sh4.y;
    o.z = (v.z - mean) * rstd * wv.z * (1.0f + sc4.z) + sh4.z;
    o.w = (v.w - mean) * rstd * wv.w * (1.0f + sc4.w) + sh4.w;
    *reinterpret_cast<float4*>(out + (size_t)row * 1024 + tid * 4) = o;
}

__global__ __launch_bounds__(256)
void memln_kernel(const float* __restrict__ hc, const float* __restrict__ ho,
                  const float* __restrict__ w, float* __restrict__ out)
{
    const int row = blockIdx.x;
    const int b = row >> 11, j = row & 2047;
    const float* src = (j < 1024) ? (hc + ((size_t)b * 1024 + j) * 1024)
                                  : (ho + ((size_t)b * 1024 + (j - 1024)) * 1024);
    const int tid = threadIdx.x;
    float4 v = *reinterpret_cast<const float4*>(src + tid * 4);
    float s  = v.x + v.y + v.z + v.w;
    float s2 = v.x * v.x + v.y * v.y + v.z * v.z + v.w * v.w;
    __shared__ float shs[8], shs2[8], stat[2];
#pragma unroll
    for (int o = 16; o; o >>= 1) {
        s  += __shfl_xor_sync(0xffffffffu, s, o);
        s2 += __shfl_xor_sync(0xffffffffu, s2, o);
    }
    if ((tid & 31) == 0) { shs[tid >> 5] = s; shs2[tid >> 5] = s2; }
    __syncthreads();
    if (tid == 0) {
        float a = 0.f, b2 = 0.f;
#pragma unroll
        for (int i = 0; i < 8; i++) { a += shs[i]; b2 += shs2[i]; }
        float mean = a * (1.0f / 1024.0f);
        float var  = b2 * (1.0f / 1024.0f) - mean * mean;
        stat[0] = mean;
        stat[1] = rsqrtf(var + 1e-5f);
    }
    __syncthreads();
    float mean = stat[0], rstd = stat[1];
    float4 wv = *reinterpret_cast<const float4*>(w + tid * 4);
    float4 o;
    o.x = (v.x - mean) * rstd * wv.x;
    o.y = (v.y - mean) * rstd * wv.y;
    o.z = (v.z - mean) * rstd * wv.z;
    o.w = (v.w - mean) * rstd * wv.w;
    *reinterpret_cast<float4*>(out + (size_t)row * 1024 + tid * 4) = o;
}

// ---------------------------------------------------------------------------
// RoPE (in place)
// ---------------------------------------------------------------------------
__global__ void rope_qk_kernel(float* __restrict__ qkv, const float* __restrict__ ct,
                               const float* __restrict__ st)
{
    const int bn = blockIdx.x;
    const int n = bn & 1023;
    const int h = threadIdx.x >> 5;
    const int d = threadIdx.x & 31;
    const float c = ct[n * 64 + d];
    const float s = st[n * 64 + d];
    float* base = qkv + (size_t)bn * 3072 + h * 64;
#pragma unroll
    for (int plane = 0; plane < 2; plane++) {
        float* p = base + plane * 1024;
        float x1 = p[d], x2 = p[d + 32];
        p[d]      = x1 * c - x2 * s;
        p[d + 32] = x2 * c + x1 * s;
    }
}

__global__ void rope_rows_kernel(float* __restrict__ x, const float* __restrict__ ct,
                                 const float* __restrict__ st, int rowlen)
{
    const int r = blockIdx.x;
    const int n = r & 1023;
    const int h = threadIdx.x >> 5;
    const int d = threadIdx.x & 31;
    const float c = ct[n * 64 + d];
    const float s = st[n * 64 + d];
    float* p = x + (size_t)r * rowlen + h * 64;
    float x1 = p[d], x2 = p[d + 32];
    p[d]      = x1 * c - x2 * s;
    p[d + 32] = x2 * c + x1 * s;
}

// ---------------------------------------------------------------------------
// Row softmax over length L
// ---------------------------------------------------------------------------
template<int L>
__global__ __launch_bounds__(256)
void softmax_kernel(float* __restrict__ S)
{
    constexpr int PER = L / 1024;
    float* p = S + (size_t)blockIdx.x * L;
    const int tid = threadIdx.x;
    float4 v[PER];
    float m = -3.4e38f;
#pragma unroll
    for (int i = 0; i < PER; i++) {
        v[i] = *reinterpret_cast<const float4*>(p + (tid + i * 256) * 4);
        m = fmaxf(m, fmaxf(fmaxf(v[i].x, v[i].y), fmaxf(v[i].z, v[i].w)));
    }
    __shared__ float smA[8], smB[8], stat[2];
#pragma unroll
    for (int o = 16; o; o >>= 1) m = fmaxf(m, __shfl_xor_sync(0xffffffffu, m, o));
    if ((tid & 31) == 0) smA[tid >> 5] = m;
    __syncthreads();
    if (tid == 0) {
        float a = smA[0];
#pragma unroll
        for (int i = 1; i < 8; i++) a = fmaxf(a, smA[i]);
        stat[0] = a;
    }
    __syncthreads();
    m = stat[0];
    float s = 0.0f;
#pragma unroll
    for (int i = 0; i < PER; i++) {
        v[i].x = __expf(v[i].x - m);
        v[i].y = __expf(v[i].y - m);
        v[i].z = __expf(v[i].z - m);
        v[i].w = __expf(v[i].w - m);
        s += v[i].x + v[i].y + v[i].z + v[i].w;
    }
#pragma unroll
    for (int o = 16; o; o >>= 1) s += __shfl_xor_sync(0xffffffffu, s, o);
    if ((tid & 31) == 0) smB[tid >> 5] = s;
    __syncthreads();
    if (tid == 0) {
        float a = 0.f;
#pragma unroll
        for (int i = 0; i < 8; i++) a += smB[i];
        stat[1] = a;
    }
    __syncthreads();
    float inv = 1.0f / stat[1];
#pragma unroll
    for (int i = 0; i < PER; i++) {
        v[i].x *= inv; v[i].y *= inv; v[i].z *= inv; v[i].w *= inv;
        *reinterpret_cast<float4*>(p + (tid + i * 256) * 4) = v[i];
    }
}

// ---------------------------------------------------------------------------
// Launch sequence
// ---------------------------------------------------------------------------
extern "C" void kernel_launch(void* const* d_in, const int* in_sizes, int n_in,
                              void* d_out, int out_size)
{
    const float* q_x        = (const float*)d_in[0];
    const float* h_content  = (const float*)d_in[1];
    const float* h_obs      = (const float*)d_in[2];
    const float* t_cond     = (const float*)d_in[3];
    const float* cosT       = (const float*)d_in[4];
    const float* sinT       = (const float*)d_in[5];
    const float* M_QQ       = (const float*)d_in[6];
    const float* M_hyb      = (const float*)d_in[7];
    const float* w_ln_self  = (const float*)d_in[8];
    const float* w_qkv      = (const float*)d_in[9];
    const float* w_self_out = (const float*)d_in[10];
    const float* w_ln_cross = (const float*)d_in[11];
    const float* w_ln_mem   = (const float*)d_in[12];
    const float* w_qproj    = (const float*)d_in[13];
    const float* w_kvproj   = (const float*)d_in[14];
    const float* w_cross_out= (const float*)d_in[15];
    const float* w_ln_mlp   = (const float*)d_in[16];
    const float* w_mlp1     = (const float*)d_in[17];
    const float* b_mlp1     = (const float*)d_in[18];
    const float* w_mlp2     = (const float*)d_in[19];
    const float* b_mlp2     = (const float*)d_in[20];
    const float* w_ada      = (const float*)d_in[21];
    const float* b_ada      = (const float*)d_in[22];
    float* out = (float*)d_out;

    float *ada, *xn, *qkv, *S, *attn, *qx1, *qc, *memln, *kv, *qx2, *hbuf;
    cudaGetSymbolAddress((void**)&ada,   g_ada);
    cudaGetSymbolAddress((void**)&xn,    g_xn);
    cudaGetSymbolAddress((void**)&qkv,   g_qkv);
    cudaGetSymbolAddress((void**)&S,     g_S);
    cudaGetSymbolAddress((void**)&attn,  g_attn);
    cudaGetSymbolAddress((void**)&qx1,   g_qx1);
    cudaGetSymbolAddress((void**)&qc,    g_qc);
    cudaGetSymbolAddress((void**)&memln, g_memln);
    cudaGetSymbolAddress((void**)&kv,    g_kv);
    cudaGetSymbolAddress((void**)&qx2,   g_qx2);
    cudaGetSymbolAddress((void**)&hbuf,  g_h);

    const float scale = 0.125f;

    // 1. ada = t_cond @ w_ada[:9216].T + b_ada
    gemm_tf32<128,128,2,4,0,0,1><<<dim3(72, 32, 1), 256>>>(
        t_cond, 0, 256, w_ada, 0, 256, ada, 0, 9216,
        4096, 9216, 256, b_ada, nullptr, nullptr, 0, nullptr, 0, 0.f);

    // 2. xn = modulate(ln(q_x))
    ln_mod_kernel<<<4096, 256>>>(q_x, w_ln_self, ada, 0 * 1024, 1 * 1024, xn);

    // 3. qkv = xn @ w_qkv.T
    gemm_tf32<128,128,2,4,0,0,0><<<dim3(24, 32, 1), 256>>>(
        xn, 0, 1024, w_qkv, 0, 1024, qkv, 0, 3072,
        4096, 3072, 1024, nullptr, nullptr, nullptr, 0, nullptr, 0, 0.f);

    // 4. RoPE q,k
    rope_qk_kernel<<<4096, 512>>>(qkv, cosT, sinT);

    // 5. self scores: S = scale*Q@K^T + M_QQ
    gemm_tf32<128,128,2,4,0,1,5><<<dim3(8, 8, 64), 256>>>(
        qkv, 1024LL * 3072, 3072, qkv + 1024, 1024LL * 3072, 3072,
        S, 1024LL * 1024, 1024,
        1024, 1024, 64, nullptr, nullptr, nullptr, 0, M_QQ, 1024, scale);

    // 6. softmax
    softmax_kernel<1024><<<65536, 256>>>(S);

    // 7. attn = P @ V
    gemm_tf32<128,64,4,2,1,2,0><<<dim3(1, 8, 64), 256>>>(
        S, 1024LL * 1024, 1024, qkv + 2048, 1024LL * 3072, 3072,
        attn, 1024LL * 1024, 1024,
        1024, 64, 1024, nullptr, nullptr, nullptr, 0, nullptr, 0, 0.f);

    // 8. qx1 = q_x + g_s * (attn @ w_self_out.T)
    gemm_tf32<128,128,2,4,0,0,3><<<dim3(8, 32, 1), 256>>>(
        attn, 0, 1024, w_self_out, 0, 1024, qx1, 0, 1024,
        4096, 1024, 1024, nullptr, q_x, ada + 2 * 1024, 9216, nullptr, 0, 0.f);

    // 9. xn = modulate(ln(qx1))
    ln_mod_kernel<<<4096, 256>>>(qx1, w_ln_cross, ada, 3 * 1024, 4 * 1024, xn);

    // 10. qc = xn @ w_qproj.T
    gemm_tf32<128,128,2,4,0,0,0><<<dim3(8, 32, 1), 256>>>(
        xn, 0, 1024, w_qproj, 0, 1024, qc, 0, 1024,
        4096, 1024, 1024, nullptr, nullptr, nullptr, 0, nullptr, 0, 0.f);

    // 11. RoPE qc
    rope_rows_kernel<<<4096, 512>>>(qc, cosT, sinT, 1024);

    // 12. memln
    memln_kernel<<<8192, 256>>>(h_content, h_obs, w_ln_mem, memln);

    // 13. kv = memln @ w_kvproj.T
    gemm_tf32<128,128,2,4,0,0,0><<<dim3(16, 64, 1), 256>>>(
        memln, 0, 1024, w_kvproj, 0, 1024, kv, 0, 2048,
        8192, 2048, 1024, nullptr, nullptr, nullptr, 0, nullptr, 0, 0.f);

    // 14. RoPE kc
    rope_rows_kernel<<<8192, 512>>>(kv, cosT, sinT, 2048);

    // 15. cross scores
    gemm_tf32<128,128,2,4,0,1,5><<<dim3(16, 8, 64), 256>>>(
        qc, 1024LL * 1024, 1024, kv, 2048LL * 2048, 2048,
        S, 1024LL * 2048, 2048,
        1024, 2048, 64, nullptr, nullptr, nullptr, 0, M_hyb, 2048, scale);

    // 16. softmax
    softmax_kernel<2048><<<65536, 256>>>(S);

    // 17. attn = P @ Vc
    gemm_tf32<128,64,4,2,1,2,0><<<dim3(1, 8, 64), 256>>>(
        S, 1024LL * 2048, 2048, kv + 1024, 2048LL * 2048, 2048,
        attn, 1024LL * 1024, 1024,
        1024, 64, 2048, nullptr, nullptr, nullptr, 0, nullptr, 0, 0.f);

    // 18. qx2 = qx1 + g_c * (attn @ w_cross_out.T)
    gemm_tf32<128,128,2,4,0,0,3><<<dim3(8, 32, 1), 256>>>(
        attn, 0, 1024, w_cross_out, 0, 1024, qx2, 0, 1024,
        4096, 1024, 1024, nullptr, qx1, ada + 5 * 1024, 9216, nullptr, 0, 0.f);

    // 19. xn = modulate(ln(qx2))
    ln_mod_kernel<<<4096, 256>>>(qx2, w_ln_mlp, ada, 6 * 1024, 7 * 1024, xn);

    // 20. h = gelu(xn @ w_mlp1.T + b_mlp1)
    gemm_tf32<128,128,2,4,0,0,2><<<dim3(32, 32, 1), 256>>>(
        xn, 0, 1024, w_mlp1, 0, 1024, hbuf, 0, 4096,
        4096, 4096, 1024, b_mlp1, nullptr, nullptr, 0, nullptr, 0, 0.f);

    // 21. out = qx2 + g_m * (h @ w_mlp2.T + b_mlp2)
    gemm_tf32<128,128,2,4,0,0,4><<<dim3(8, 32, 1), 256>>>(
        hbuf, 0, 4096, w_mlp2, 0, 4096, out, 0, 1024,
        4096, 1024, 4096, b_mlp2, qx2, ada + 8 * 1024, 9216, nullptr, 0, 0.f);
}